// round 6
// baseline (speedup 1.0000x reference)
#include <cuda_runtime.h>
#include <cuda_bf16.h>

// One-pole IIR, time-chunked with decayed-halo warm-up.
//   out[t] = b0*x[t] + s ;  s' = (b1 + a1*b0)*x[t] + a1*s
// Each thread owns 4 columns (float4) -> 4 independent FMA chains, and
// explicitly batches TILE independent 16B loads before running the dependent
// chain (guaranteed MLP). 128 time-chunks run in parallel; each non-initial
// chunk warms up from s=0 over W halo rows where |a1|^W <= 1e-6 (truncation
// ~1e-6 relative, vs the 1e-3 test gate).

#define TILE 8
#define CHUNKS 128

__global__ void __launch_bounds__(128) onepole_v4_kernel(
    const float4* __restrict__ x,
    const float4* __restrict__ state,
    const float* __restrict__ b0p,
    const float* __restrict__ b1p,
    const float* __restrict__ a1p,
    float4* __restrict__ out,
    int T, int B4, int L, int write_final)
{
    int c = blockIdx.x * blockDim.x + threadIdx.x;
    if (c >= B4) return;
    int t0 = blockIdx.y * L;
    if (t0 >= T) return;
    int t1 = t0 + L; if (t1 > T) t1 = T;

    float b0 = __ldg(b0p);
    float b1 = __ldg(b1p);
    float a1 = __ldg(a1p);
    a1 = fminf(1.0f, fmaxf(-1.0f, a1));        // reference clamps a1
    const float aa = fabsf(a1);
    const float cc = fmaf(a1, b0, b1);

    // Warm-up length: smallest W with |a1|^W <= 1e-6 (runtime-adaptive).
    int W;
    if (aa < 1e-30f)       W = 0;
    else if (aa > 0.999f)  W = t0;             // near-|1|: exact full warm-up
    else {
        W = (int)ceilf(-13.9f / logf(aa));     // ln(1e-6) = -13.82
        if (W > t0) W = t0;
    }

    const int tw = t0 - W;
    float4 s;
    if (tw == 0) s = state[c];                 // exact initial state
    else         s = make_float4(0.f, 0.f, 0.f, 0.f);

    const float4* __restrict__ xp = x + (size_t)tw * (size_t)B4 + c;

    // ---- Halo warm-up: batched loads, no stores ----
    int t = tw;
    for (; t + TILE <= t0; t += TILE) {
        float4 v[TILE];
        #pragma unroll
        for (int j = 0; j < TILE; ++j) v[j] = __ldcs(xp + (size_t)j * B4);
        xp += (size_t)TILE * B4;
        #pragma unroll
        for (int j = 0; j < TILE; ++j) {
            s.x = fmaf(a1, s.x, cc * v[j].x);
            s.y = fmaf(a1, s.y, cc * v[j].y);
            s.z = fmaf(a1, s.z, cc * v[j].z);
            s.w = fmaf(a1, s.w, cc * v[j].w);
        }
    }
    for (; t < t0; ++t) {
        float4 v = __ldcs(xp); xp += B4;
        s.x = fmaf(a1, s.x, cc * v.x);
        s.y = fmaf(a1, s.y, cc * v.y);
        s.z = fmaf(a1, s.z, cc * v.z);
        s.w = fmaf(a1, s.w, cc * v.w);
    }

    // ---- Main chunk: batch TILE loads, then chain + stores ----
    float4* __restrict__ yp = out + (size_t)t0 * (size_t)B4 + c;
    t = t0;
    for (; t + TILE <= t1; t += TILE) {
        float4 v[TILE];
        #pragma unroll
        for (int j = 0; j < TILE; ++j) v[j] = __ldcs(xp + (size_t)j * B4);
        xp += (size_t)TILE * B4;
        #pragma unroll
        for (int j = 0; j < TILE; ++j) {
            float4 o;
            o.x = fmaf(b0, v[j].x, s.x);
            o.y = fmaf(b0, v[j].y, s.y);
            o.z = fmaf(b0, v[j].z, s.z);
            o.w = fmaf(b0, v[j].w, s.w);
            __stcs(yp + (size_t)j * B4, o);
            s.x = fmaf(a1, s.x, cc * v[j].x);
            s.y = fmaf(a1, s.y, cc * v[j].y);
            s.z = fmaf(a1, s.z, cc * v[j].z);
            s.w = fmaf(a1, s.w, cc * v[j].w);
        }
        yp += (size_t)TILE * B4;
    }
    for (; t < t1; ++t) {
        float4 v = __ldcs(xp); xp += B4;
        float4 o;
        o.x = fmaf(b0, v.x, s.x);
        o.y = fmaf(b0, v.y, s.y);
        o.z = fmaf(b0, v.z, s.z);
        o.w = fmaf(b0, v.w, s.w);
        __stcs(yp, o); yp += B4;
        s.x = fmaf(a1, s.x, cc * v.x);
        s.y = fmaf(a1, s.y, cc * v.y);
        s.z = fmaf(a1, s.z, cc * v.z);
        s.w = fmaf(a1, s.w, cc * v.w);
    }

    if (write_final && t1 == T) {
        out[(size_t)T * (size_t)B4 + c] = s;
    }
}

// Scalar fallback for B not divisible by 4 (correctness safety net).
__global__ void __launch_bounds__(256) onepole_scalar_kernel(
    const float* __restrict__ x,
    const float* __restrict__ state,
    const float* __restrict__ b0p,
    const float* __restrict__ b1p,
    const float* __restrict__ a1p,
    float* __restrict__ out,
    int T, int B, int L, int write_final)
{
    int col = blockIdx.x * blockDim.x + threadIdx.x;
    if (col >= B) return;
    int t0 = blockIdx.y * L;
    if (t0 >= T) return;
    int t1 = t0 + L; if (t1 > T) t1 = T;

    float b0 = b0p[0], b1 = b1p[0], a1 = a1p[0];
    a1 = fminf(1.0f, fmaxf(-1.0f, a1));
    const float aa = fabsf(a1);
    const float cc = fmaf(a1, b0, b1);

    int W;
    if (aa < 1e-30f)       W = 0;
    else if (aa > 0.999f)  W = t0;
    else { W = (int)ceilf(-13.9f / logf(aa)); if (W > t0) W = t0; }

    const int tw = t0 - W;
    float s = (tw == 0) ? state[col] : 0.0f;
    const float* __restrict__ xp = x + (size_t)tw * (size_t)B + col;

    for (int t = tw; t < t0; ++t) { float v = *xp; xp += B; s = fmaf(a1, s, cc * v); }

    float* __restrict__ yp = out + (size_t)t0 * (size_t)B + col;
    for (int t = t0; t < t1; ++t) {
        float v = *xp; xp += B;
        float o = fmaf(b0, v, s);
        *yp = o; yp += B;
        s = fmaf(a1, s, cc * v);
    }
    if (write_final && t1 == T) out[(size_t)T * (size_t)B + col] = s;
}

extern "C" void kernel_launch(void* const* d_in, const int* in_sizes, int n_in,
                              void* d_out, int out_size)
{
    const float* x     = (const float*)d_in[0];
    const float* state = (const float*)d_in[1];
    const float* b0    = (const float*)d_in[2];
    const float* b1    = (const float*)d_in[3];
    const float* a1    = (const float*)d_in[4];
    float* out = (float*)d_out;

    const int B = in_sizes[1];            // state has B elements
    const int T = in_sizes[0] / B;        // x is [T, B]
    const int write_final = (out_size >= T * B + B) ? 1 : 0;

    int L = (T + CHUNKS - 1) / CHUNKS;
    if (L < TILE) L = TILE;               // keep chunks at least one tile long
    int nchunks = (T + L - 1) / L;

    if ((B & 3) == 0) {
        const int B4 = B >> 2;
        dim3 block(128);
        dim3 grid((B4 + 127) / 128, nchunks);
        onepole_v4_kernel<<<grid, block>>>(
            (const float4*)x, (const float4*)state, b0, b1, a1,
            (float4*)out, T, B4, L, write_final);
    } else {
        dim3 block(256);
        dim3 grid((B + 255) / 256, nchunks);
        onepole_scalar_kernel<<<grid, block>>>(x, state, b0, b1, a1, out,
                                               T, B, L, write_final);
    }
}

// round 7
// speedup vs baseline: 1.0318x; 1.0318x over previous
#include <cuda_runtime.h>
#include <cuda_bf16.h>

// One-pole IIR, time-chunked with decayed-halo warm-up.
//   out[t] = b0*x[t] + s ;  s' = (b1 + a1*b0)*x[t] + a1*s
// Each thread owns 4 columns (float4) -> 4 independent FMA chains, and
// explicitly batches TILE independent 16B loads before running the dependent
// chain (guaranteed MLP). Measurement (R4 vs R6): 5.8-6.0 TB/s is the memory
// ceiling regardless of occupancy (21% vs 40% -> same BW), so this round
// minimizes BYTES: 64 chunks and a 1e-5 decay threshold (W=17 for a1=0.5,
// truncation ~2.5e-7 global rel err vs the 1e-3 gate).

#define TILE 8
#define CHUNKS 64

__global__ void __launch_bounds__(128) onepole_v4_kernel(
    const float4* __restrict__ x,
    const float4* __restrict__ state,
    const float* __restrict__ b0p,
    const float* __restrict__ b1p,
    const float* __restrict__ a1p,
    float4* __restrict__ out,
    int T, int B4, int L, int write_final)
{
    int c = blockIdx.x * blockDim.x + threadIdx.x;
    if (c >= B4) return;
    int t0 = blockIdx.y * L;
    if (t0 >= T) return;
    int t1 = t0 + L; if (t1 > T) t1 = T;

    float b0 = __ldg(b0p);
    float b1 = __ldg(b1p);
    float a1 = __ldg(a1p);
    a1 = fminf(1.0f, fmaxf(-1.0f, a1));        // reference clamps a1
    const float aa = fabsf(a1);
    const float cc = fmaf(a1, b0, b1);

    // Warm-up length: smallest W with |a1|^W <= 1e-5 (runtime-adaptive).
    int W;
    if (aa < 1e-30f)       W = 0;
    else if (aa > 0.999f)  W = t0;             // near-|1|: exact full warm-up
    else {
        W = (int)ceilf(-11.6f / logf(aa));     // ln(1e-5) = -11.51
        if (W > t0) W = t0;
    }

    const int tw = t0 - W;
    float4 s;
    if (tw == 0) s = state[c];                 // exact initial state
    else         s = make_float4(0.f, 0.f, 0.f, 0.f);

    const float4* __restrict__ xp = x + (size_t)tw * (size_t)B4 + c;

    // ---- Halo warm-up: batched loads, no stores ----
    int t = tw;
    for (; t + TILE <= t0; t += TILE) {
        float4 v[TILE];
        #pragma unroll
        for (int j = 0; j < TILE; ++j) v[j] = __ldcs(xp + (size_t)j * B4);
        xp += (size_t)TILE * B4;
        #pragma unroll
        for (int j = 0; j < TILE; ++j) {
            s.x = fmaf(a1, s.x, cc * v[j].x);
            s.y = fmaf(a1, s.y, cc * v[j].y);
            s.z = fmaf(a1, s.z, cc * v[j].z);
            s.w = fmaf(a1, s.w, cc * v[j].w);
        }
    }
    for (; t < t0; ++t) {
        float4 v = __ldcs(xp); xp += B4;
        s.x = fmaf(a1, s.x, cc * v.x);
        s.y = fmaf(a1, s.y, cc * v.y);
        s.z = fmaf(a1, s.z, cc * v.z);
        s.w = fmaf(a1, s.w, cc * v.w);
    }

    // ---- Main chunk: batch TILE loads, then chain + stores ----
    float4* __restrict__ yp = out + (size_t)t0 * (size_t)B4 + c;
    t = t0;
    for (; t + TILE <= t1; t += TILE) {
        float4 v[TILE];
        #pragma unroll
        for (int j = 0; j < TILE; ++j) v[j] = __ldcs(xp + (size_t)j * B4);
        xp += (size_t)TILE * B4;
        #pragma unroll
        for (int j = 0; j < TILE; ++j) {
            float4 o;
            o.x = fmaf(b0, v[j].x, s.x);
            o.y = fmaf(b0, v[j].y, s.y);
            o.z = fmaf(b0, v[j].z, s.z);
            o.w = fmaf(b0, v[j].w, s.w);
            __stcs(yp + (size_t)j * B4, o);
            s.x = fmaf(a1, s.x, cc * v[j].x);
            s.y = fmaf(a1, s.y, cc * v[j].y);
            s.z = fmaf(a1, s.z, cc * v[j].z);
            s.w = fmaf(a1, s.w, cc * v[j].w);
        }
        yp += (size_t)TILE * B4;
    }
    for (; t < t1; ++t) {
        float4 v = __ldcs(xp); xp += B4;
        float4 o;
        o.x = fmaf(b0, v.x, s.x);
        o.y = fmaf(b0, v.y, s.y);
        o.z = fmaf(b0, v.z, s.z);
        o.w = fmaf(b0, v.w, s.w);
        __stcs(yp, o); yp += B4;
        s.x = fmaf(a1, s.x, cc * v.x);
        s.y = fmaf(a1, s.y, cc * v.y);
        s.z = fmaf(a1, s.z, cc * v.z);
        s.w = fmaf(a1, s.w, cc * v.w);
    }

    if (write_final && t1 == T) {
        out[(size_t)T * (size_t)B4 + c] = s;
    }
}

// Scalar fallback for B not divisible by 4 (correctness safety net).
__global__ void __launch_bounds__(256) onepole_scalar_kernel(
    const float* __restrict__ x,
    const float* __restrict__ state,
    const float* __restrict__ b0p,
    const float* __restrict__ b1p,
    const float* __restrict__ a1p,
    float* __restrict__ out,
    int T, int B, int L, int write_final)
{
    int col = blockIdx.x * blockDim.x + threadIdx.x;
    if (col >= B) return;
    int t0 = blockIdx.y * L;
    if (t0 >= T) return;
    int t1 = t0 + L; if (t1 > T) t1 = T;

    float b0 = b0p[0], b1 = b1p[0], a1 = a1p[0];
    a1 = fminf(1.0f, fmaxf(-1.0f, a1));
    const float aa = fabsf(a1);
    const float cc = fmaf(a1, b0, b1);

    int W;
    if (aa < 1e-30f)       W = 0;
    else if (aa > 0.999f)  W = t0;
    else { W = (int)ceilf(-11.6f / logf(aa)); if (W > t0) W = t0; }

    const int tw = t0 - W;
    float s = (tw == 0) ? state[col] : 0.0f;
    const float* __restrict__ xp = x + (size_t)tw * (size_t)B + col;

    for (int t = tw; t < t0; ++t) { float v = *xp; xp += B; s = fmaf(a1, s, cc * v); }

    float* __restrict__ yp = out + (size_t)t0 * (size_t)B + col;
    for (int t = t0; t < t1; ++t) {
        float v = *xp; xp += B;
        float o = fmaf(b0, v, s);
        *yp = o; yp += B;
        s = fmaf(a1, s, cc * v);
    }
    if (write_final && t1 == T) out[(size_t)T * (size_t)B + col] = s;
}

extern "C" void kernel_launch(void* const* d_in, const int* in_sizes, int n_in,
                              void* d_out, int out_size)
{
    const float* x     = (const float*)d_in[0];
    const float* state = (const float*)d_in[1];
    const float* b0    = (const float*)d_in[2];
    const float* b1    = (const float*)d_in[3];
    const float* a1    = (const float*)d_in[4];
    float* out = (float*)d_out;

    const int B = in_sizes[1];            // state has B elements
    const int T = in_sizes[0] / B;        // x is [T, B]
    const int write_final = (out_size >= T * B + B) ? 1 : 0;

    int L = (T + CHUNKS - 1) / CHUNKS;
    if (L < TILE) L = TILE;               // keep chunks at least one tile long
    int nchunks = (T + L - 1) / L;

    if ((B & 3) == 0) {
        const int B4 = B >> 2;
        dim3 block(128);
        dim3 grid((B4 + 127) / 128, nchunks);
        onepole_v4_kernel<<<grid, block>>>(
            (const float4*)x, (const float4*)state, b0, b1, a1,
            (float4*)out, T, B4, L, write_final);
    } else {
        dim3 block(256);
        dim3 grid((B + 255) / 256, nchunks);
        onepole_scalar_kernel<<<grid, block>>>(x, state, b0, b1, a1, out,
                                               T, B, L, write_final);
    }
}